// round 1
// baseline (speedup 1.0000x reference)
#include <cuda_runtime.h>
#include <cuda_bf16.h>

// ---------------------------------------------------------------------------
// Problem constants
// ---------------------------------------------------------------------------
#define NPIX 2304      // N = 48*48
#define CDIM 128       // channels
#define NH   4         // heads
#define HC   32        // head channels
#define NCLUST 16      // clusters
#define HID  256       // mlp hidden = 2C

// ---------------------------------------------------------------------------
// Device scratch (allocation-free rule: __device__ globals)
// ---------------------------------------------------------------------------
__device__ float g_q[NPIX * CDIM];
__device__ float g_k[NPIX * CDIM];
__device__ float g_v[NPIX * CDIM];
__device__ float g_cacc[NCLUST * CDIM];
__device__ float g_ccnt[NCLUST];
__device__ float g_centers[NCLUST * CDIM];
__device__ float g_attn[NPIX * CDIM];
__device__ float g_h1[NPIX * HID];
__device__ float g_rs1[NPIX * CDIM];
__device__ float g_h2[NPIX * HID];

// ---------------------------------------------------------------------------
// Generic tiled GEMM:  C = act(A @ W + b) (+ res), optional transposed A read
// (A stored [K][M], i.e. channel-major image) and transposed C write.
// BM=64, BN=64, BK=16, 256 threads, 4x4 register microtile.
// ---------------------------------------------------------------------------
#define BM 64
#define BN 64
#define BK 16

template <bool TRANSA, bool LEAKY, bool TRANSOUT>
__global__ void __launch_bounds__(256) gemm_k(
    const float* __restrict__ A, const float* __restrict__ W,
    const float* __restrict__ bias, const float* __restrict__ res,
    float* __restrict__ C, int M, int Kd, int Nout)
{
    __shared__ float As[BK][BM + 4];
    __shared__ float Ws[BK][BN + 4];

    const int tid = threadIdx.x;
    const int tx = tid & 15;   // -> n
    const int ty = tid >> 4;   // -> m
    const int m0 = blockIdx.y * BM;
    const int n0 = blockIdx.x * BN;

    float acc[4][4] = {};

    for (int k0 = 0; k0 < Kd; k0 += BK) {
        if (TRANSA) {
            #pragma unroll
            for (int idx = tid; idx < BM * BK; idx += 256) {
                int kk = idx >> 6, r = idx & 63;
                As[kk][r] = A[(k0 + kk) * M + m0 + r];
            }
        } else {
            #pragma unroll
            for (int idx = tid; idx < BM * BK; idx += 256) {
                int r = idx >> 4, kk = idx & 15;
                As[kk][r] = A[(m0 + r) * Kd + k0 + kk];
            }
        }
        #pragma unroll
        for (int idx = tid; idx < BK * BN; idx += 256) {
            int kk = idx >> 6, c = idx & 63;
            Ws[kk][c] = W[(k0 + kk) * Nout + n0 + c];
        }
        __syncthreads();

        #pragma unroll
        for (int kk = 0; kk < BK; kk++) {
            float4 a4 = *(const float4*)&As[kk][ty * 4];
            float4 b4 = *(const float4*)&Ws[kk][tx * 4];
            float av[4] = {a4.x, a4.y, a4.z, a4.w};
            float bv[4] = {b4.x, b4.y, b4.z, b4.w};
            #pragma unroll
            for (int i = 0; i < 4; i++)
                #pragma unroll
                for (int j = 0; j < 4; j++)
                    acc[i][j] += av[i] * bv[j];
        }
        __syncthreads();
    }

    const int mb = m0 + ty * 4;
    const int nb = n0 + tx * 4;
    float4 bq = *(const float4*)&bias[nb];
    float bvv[4] = {bq.x, bq.y, bq.z, bq.w};

    if (!TRANSOUT) {
        #pragma unroll
        for (int i = 0; i < 4; i++) {
            float4 o;
            float* op = (float*)&o;
            float rr[4] = {0.f, 0.f, 0.f, 0.f};
            if (res) {
                float4 r4 = *(const float4*)&res[(mb + i) * Nout + nb];
                rr[0] = r4.x; rr[1] = r4.y; rr[2] = r4.z; rr[3] = r4.w;
            }
            #pragma unroll
            for (int j = 0; j < 4; j++) {
                float val = acc[i][j] + bvv[j];
                if (LEAKY) val = val > 0.f ? val : 0.01f * val;
                val += rr[j];
                op[j] = val;
            }
            *(float4*)&C[(mb + i) * Nout + nb] = o;
        }
    } else {
        #pragma unroll
        for (int j = 0; j < 4; j++) {
            float4 o;
            float* op = (float*)&o;
            #pragma unroll
            for (int i = 0; i < 4; i++) {
                float val = acc[i][j] + bvv[j];
                if (LEAKY) val = val > 0.f ? val : 0.01f * val;
                if (res) val += res[(mb + i) * Nout + nb + j];
                op[i] = val;
            }
            *(float4*)&C[(nb + j) * M + mb] = o;
        }
    }
}

// ---------------------------------------------------------------------------
// Cluster centers: zero -> accumulate (16 blocks x 128 threads) -> normalize
// ---------------------------------------------------------------------------
__global__ void centers_zero_k()
{
    int t = blockIdx.x * blockDim.x + threadIdx.x;
    if (t < NCLUST * CDIM) g_cacc[t] = 0.f;
    if (t < NCLUST) g_ccnt[t] = 0.f;
}

__global__ void __launch_bounds__(128) centers_accum_k(const int* __restrict__ labels)
{
    __shared__ float sacc[NCLUST * CDIM];
    const int c = threadIdx.x;
    #pragma unroll
    for (int kk = 0; kk < NCLUST; kk++) sacc[kk * CDIM + c] = 0.f;

    const int n0 = blockIdx.x * (NPIX / 16);
    float cnt = 0.f;
    for (int n = n0; n < n0 + (NPIX / 16); n++) {
        int lab = labels[n];
        sacc[lab * CDIM + c] += g_k[n * CDIM + c];
        if (c == lab) cnt += 1.f;
    }
    #pragma unroll
    for (int kk = 0; kk < NCLUST; kk++)
        atomicAdd(&g_cacc[kk * CDIM + c], sacc[kk * CDIM + c]);
    if (c < NCLUST) atomicAdd(&g_ccnt[c], cnt);
}

__global__ void centers_norm_k()
{
    int t = blockIdx.x * blockDim.x + threadIdx.x;
    if (t < NCLUST * CDIM) {
        int kk = t >> 7;
        g_centers[t] = g_cacc[t] / (g_ccnt[kk] + 1e-6f);
    }
}

// ---------------------------------------------------------------------------
// Attention: block = (32-query tile, head). Online softmax over 64-key tiles.
// Cross-cluster scores = center_score * pc (cheap, uniform); same-cluster
// pairs compacted into a list and processed warp-coherently (8 thr / pair).
// ---------------------------------------------------------------------------
__global__ void __launch_bounds__(256) attn_k(
    const float* __restrict__ q, const float* __restrict__ k,
    const float* __restrict__ v, const float* __restrict__ centers,
    const float* __restrict__ pc, const int* __restrict__ labels,
    float* __restrict__ out)
{
    const int h  = blockIdx.y;
    const int i0 = blockIdx.x * 32;
    const int tid = threadIdx.x;

    __shared__ float qs[32][32];
    __shared__ float cks[16][32];
    __shared__ float css[32][16];
    __shared__ float ks[64][32];
    __shared__ float vs[64][32];
    __shared__ float pcs[32][64];
    __shared__ float sS[32][64];
    __shared__ unsigned short pairbuf[2048];
    __shared__ int   labq[32];
    __shared__ int   labj[64];
    __shared__ float mbuf[32];
    __shared__ float lbuf[32];
    __shared__ int   nIntra;

    // prologue: q tile + center head-slice + query labels
    #pragma unroll
    for (int idx = tid; idx < 1024; idx += 256) {
        int qi = idx >> 5, d = idx & 31;
        qs[qi][d] = q[(i0 + qi) * CDIM + h * HC + d];
    }
    #pragma unroll
    for (int idx = tid; idx < 512; idx += 256) {
        int kk = idx >> 5, d = idx & 31;
        cks[kk][d] = centers[kk * CDIM + h * HC + d];
    }
    if (tid < 32) {
        labq[tid] = labels[i0 + tid];
        mbuf[tid] = -1e30f;
        lbuf[tid] = 0.f;
    }
    __syncthreads();

    // center scores css[qi][kk] = q_i . center_kk (head slice)
    for (int r = tid; r < 512; r += 256) {
        int qi = r >> 4, kk = r & 15;
        float s = 0.f;
        #pragma unroll
        for (int d = 0; d < 32; d++) s += qs[qi][d] * cks[kk][d];
        css[qi][kk] = s;
    }

    const int qi = tid >> 3;   // 0..31
    const int dg = tid & 7;    // 0..7 -> d = dg*4..dg*4+3
    float4 acc = {0.f, 0.f, 0.f, 0.f};
    const float invScale = 0.17677669529663687f;  // 1/sqrt(32)

    for (int j0 = 0; j0 < NPIX; j0 += 64) {
        __syncthreads();   // previous tile PV done before overwriting tiles

        #pragma unroll
        for (int idx = tid; idx < 2048; idx += 256) {
            int j = idx >> 5, d = idx & 31;
            ks[j][d] = k[(j0 + j) * CDIM + h * HC + d];
            vs[j][d] = v[(j0 + j) * CDIM + h * HC + d];
        }
        #pragma unroll
        for (int idx = tid; idx < 2048; idx += 256) {
            int qq = idx >> 6, jj = idx & 63;
            pcs[qq][jj] = pc[(i0 + qq) * NPIX + j0 + jj];
        }
        if (tid < 64) labj[tid] = labels[j0 + tid];
        if (tid == 0) nIntra = 0;
        __syncthreads();

        // inter scores (uniform) + compact intra pairs
        #pragma unroll
        for (int idx = tid; idx < 2048; idx += 256) {
            int qq = idx >> 6, jj = idx & 63;
            int lj = labj[jj];
            if (lj == labq[qq]) {
                int pos = atomicAdd(&nIntra, 1);
                pairbuf[pos] = (unsigned short)((qq << 6) | jj);
            } else {
                sS[qq][jj] = css[qq][lj] * pcs[qq][jj] * invScale;
            }
        }
        __syncthreads();

        // intra pairs: 8 threads per pair, shuffle-reduced dot32
        const int nI = nIntra;
        for (int base = 0; base < nI; base += 32) {
            int pi = base + (tid >> 3);
            int g  = tid & 7;
            float partial = 0.f;
            int pq = 0, pj = 0;
            if (pi < nI) {
                int code = pairbuf[pi];
                pq = code >> 6; pj = code & 63;
                float4 a = *(const float4*)&qs[pq][g * 4];
                float4 b = *(const float4*)&ks[pj][g * 4];
                partial = a.x * b.x + a.y * b.y + a.z * b.z + a.w * b.w;
            }
            partial += __shfl_xor_sync(0xffffffffu, partial, 1);
            partial += __shfl_xor_sync(0xffffffffu, partial, 2);
            partial += __shfl_xor_sync(0xffffffffu, partial, 4);
            if (pi < nI && g == 0) sS[pq][pj] = partial * invScale;
        }
        __syncthreads();

        // online softmax update (8 threads per query, same-warp group)
        float mloc = -1e30f;
        #pragma unroll
        for (int r = 0; r < 8; r++) mloc = fmaxf(mloc, sS[qi][dg * 8 + r]);
        mloc = fmaxf(mloc, __shfl_xor_sync(0xffffffffu, mloc, 1));
        mloc = fmaxf(mloc, __shfl_xor_sync(0xffffffffu, mloc, 2));
        mloc = fmaxf(mloc, __shfl_xor_sync(0xffffffffu, mloc, 4));
        float mold = mbuf[qi];
        float mnew = fmaxf(mold, mloc);
        float factor = __expf(mold - mnew);
        float psum = 0.f;
        #pragma unroll
        for (int r = 0; r < 8; r++) {
            float p = __expf(sS[qi][dg * 8 + r] - mnew);
            sS[qi][dg * 8 + r] = p;
            psum += p;
        }
        psum += __shfl_xor_sync(0xffffffffu, psum, 1);
        psum += __shfl_xor_sync(0xffffffffu, psum, 2);
        psum += __shfl_xor_sync(0xffffffffu, psum, 4);
        if (dg == 0) {
            mbuf[qi] = mnew;
            lbuf[qi] = lbuf[qi] * factor + psum;
        }
        __syncwarp();

        // PV accumulate
        acc.x *= factor; acc.y *= factor; acc.z *= factor; acc.w *= factor;
        #pragma unroll 8
        for (int jj = 0; jj < 64; jj++) {
            float p = sS[qi][jj];
            float4 vv = *(const float4*)&vs[jj][dg * 4];
            acc.x += p * vv.x; acc.y += p * vv.y;
            acc.z += p * vv.z; acc.w += p * vv.w;
        }
    }

    __syncthreads();
    float linv = 1.0f / lbuf[qi];
    float4 o = {acc.x * linv, acc.y * linv, acc.z * linv, acc.w * linv};
    *(float4*)&out[(i0 + qi) * CDIM + h * HC + dg * 4] = o;
}

// ---------------------------------------------------------------------------
// Host orchestration
// ---------------------------------------------------------------------------
extern "C" void kernel_launch(void* const* d_in, const int* in_sizes, int n_in,
                              void* d_out, int out_size)
{
    // Input order detection: dict order has labels (2304 ints) at index 4;
    // signature order puts labels last (index 18).
    const bool dictOrder = (in_sizes[4] == NPIX);
    const int wb = dictOrder ? 5 : 4;

    const float* q_img = (const float*)d_in[0];
    const float* k_img = (const float*)d_in[1];
    const float* v_img = (const float*)d_in[2];
    const float* pc    = (const float*)d_in[3];
    const int*   labels = (const int*)d_in[dictOrder ? 4 : 18];

    const float* wq  = (const float*)d_in[wb + 0];
    const float* bq  = (const float*)d_in[wb + 1];
    const float* wk  = (const float*)d_in[wb + 2];
    const float* bk  = (const float*)d_in[wb + 3];
    const float* wv  = (const float*)d_in[wb + 4];
    const float* bv  = (const float*)d_in[wb + 5];
    const float* w1a = (const float*)d_in[wb + 6];
    const float* b1a = (const float*)d_in[wb + 7];
    const float* w1b = (const float*)d_in[wb + 8];
    const float* b1b = (const float*)d_in[wb + 9];
    const float* w2a = (const float*)d_in[wb + 10];
    const float* b2a = (const float*)d_in[wb + 11];
    const float* w2b = (const float*)d_in[wb + 12];
    const float* b2b = (const float*)d_in[wb + 13];
    float* out = (float*)d_out;

    void* p;
    cudaGetSymbolAddress(&p, g_q);       float* pq  = (float*)p;
    cudaGetSymbolAddress(&p, g_k);       float* pk  = (float*)p;
    cudaGetSymbolAddress(&p, g_v);       float* pv  = (float*)p;
    cudaGetSymbolAddress(&p, g_centers); float* pce = (float*)p;
    cudaGetSymbolAddress(&p, g_attn);    float* pat = (float*)p;
    cudaGetSymbolAddress(&p, g_h1);      float* ph1 = (float*)p;
    cudaGetSymbolAddress(&p, g_rs1);     float* pr1 = (float*)p;
    cudaGetSymbolAddress(&p, g_h2);      float* ph2 = (float*)p;

    dim3 blk(256);
    dim3 gProj(CDIM / BN, NPIX / BM);   // (2, 36)
    dim3 gHid(HID / BN, NPIX / BM);     // (4, 36)

    // projections (img is channel-major -> TRANSA read)
    gemm_k<true, false, false><<<gProj, blk>>>(q_img, wq, bq, nullptr, pq, NPIX, CDIM, CDIM);
    gemm_k<true, false, false><<<gProj, blk>>>(k_img, wk, bk, nullptr, pk, NPIX, CDIM, CDIM);
    gemm_k<true, false, false><<<gProj, blk>>>(v_img, wv, bv, nullptr, pv, NPIX, CDIM, CDIM);

    // cluster centers from projected k
    centers_zero_k<<<8, 256>>>();
    centers_accum_k<<<16, 128>>>(labels);
    centers_norm_k<<<8, 256>>>();

    // attention
    attn_k<<<dim3(NPIX / 32, NH), blk>>>(pq, pk, pv, pce, pc, labels, pat);

    // mlp_1 with residual v, mlp_2 with residual rs1 (transposed final write)
    gemm_k<false, true,  false><<<gHid,  blk>>>(pat, w1a, b1a, nullptr, ph1, NPIX, CDIM, HID);
    gemm_k<false, false, false><<<gProj, blk>>>(ph1, w1b, b1b, pv,      pr1, NPIX, HID, CDIM);
    gemm_k<false, true,  false><<<gHid,  blk>>>(pr1, w2a, b2a, nullptr, ph2, NPIX, CDIM, HID);
    gemm_k<false, false, true ><<<gProj, blk>>>(ph2, w2b, b2b, pr1,     out, NPIX, HID, CDIM);
}